// round 3
// baseline (speedup 1.0000x reference)
#include <cuda_runtime.h>
#include <math.h>

#define Bb 64
#define Nn 1024
#define Fdim 64
#define DEG 8
#define ALPHA 0.2f

// Scratch (static __device__ globals — allocation-free per harness rules)
__device__ __align__(16) float g_h[Bb * Nn * Fdim];    // 16 MB: h = atoms @ W
__device__ float g_s1[Bb * Nn];                        // h @ a1
__device__ float g_s2[Bb * Nn];                        // h @ a2

// ---------------------------------------------------------------------------
// Kernel 1: h = atoms @ W  (65536 x 64 x 64), fused s1/s2 epilogue.
// Block = 256 threads handles 64 rows. Thread (tr, tc) computes a 4x4 tile.
// atoms tile stored K-major (transposed) in smem so the inner loop is two
// LDS.128 + 16 FFMA per k.
// ---------------------------------------------------------------------------
__global__ __launch_bounds__(256) void gat_gemm(const float* __restrict__ atoms,
                                                const float* __restrict__ W,
                                                const float* __restrict__ a)
{
    __shared__ __align__(16) float sW[64 * 64];      // [k][c]
    __shared__ __align__(16) float sAT[64 * 68];     // [k][row], pad 68: 16B-aligned rows, spreads banks

    const int tid  = threadIdx.x;
    const int row0 = blockIdx.x * 64;

    // Load W (row-major [F_IN][F_OUT] == [k][c], matches einsum 'bnf,fo->bno')
    #pragma unroll
    for (int i = tid; i < 4096; i += 256) sW[i] = W[i];

    // Load 64 atom rows, transposed into sAT[k][r]
    #pragma unroll
    for (int i = tid; i < 4096; i += 256) {
        int r = i >> 6, k = i & 63;
        sAT[k * 68 + r] = atoms[(size_t)(row0 + r) * 64 + k];
    }
    __syncthreads();

    const int tc = tid & 15;   // column group: cols 4*tc .. 4*tc+3
    const int tr = tid >> 4;   // row group:    rows 4*tr .. 4*tr+3

    float acc[4][4];
    #pragma unroll
    for (int r = 0; r < 4; r++)
        #pragma unroll
        for (int c = 0; c < 4; c++) acc[r][c] = 0.f;

    #pragma unroll 16
    for (int k = 0; k < 64; k++) {
        float4 av = *reinterpret_cast<const float4*>(&sAT[k * 68 + tr * 4]);
        float4 wv = *reinterpret_cast<const float4*>(&sW[k * 64 + tc * 4]);
        float ar[4] = {av.x, av.y, av.z, av.w};
        float wr[4] = {wv.x, wv.y, wv.z, wv.w};
        #pragma unroll
        for (int r = 0; r < 4; r++)
            #pragma unroll
            for (int c = 0; c < 4; c++) acc[r][c] = fmaf(ar[r], wr[c], acc[r][c]);
    }

    // Store h (float4, coalesced: 16 threads cover one 64-col row)
    #pragma unroll
    for (int r = 0; r < 4; r++) {
        float4 v = make_float4(acc[r][0], acc[r][1], acc[r][2], acc[r][3]);
        *reinterpret_cast<float4*>(&g_h[(size_t)(row0 + tr * 4 + r) * 64 + tc * 4]) = v;
    }

    // Fused s1/s2: per-thread partial dot over its 4 cols, then butterfly
    // reduce across the 16-lane column groups (deterministic, no atomics).
    float a1v[4], a2v[4];
    #pragma unroll
    for (int c = 0; c < 4; c++) {
        a1v[c] = a[tc * 4 + c];
        a2v[c] = a[64 + tc * 4 + c];
    }
    #pragma unroll
    for (int r = 0; r < 4; r++) {
        float p1 = 0.f, p2 = 0.f;
        #pragma unroll
        for (int c = 0; c < 4; c++) {
            p1 = fmaf(acc[r][c], a1v[c], p1);
            p2 = fmaf(acc[r][c], a2v[c], p2);
        }
        #pragma unroll
        for (int off = 8; off > 0; off >>= 1) {
            p1 += __shfl_xor_sync(0xffffffffu, p1, off);
            p2 += __shfl_xor_sync(0xffffffffu, p2, off);
        }
        if (tc == 0) {
            g_s1[row0 + tr * 4 + r] = p1;
            g_s2[row0 + tr * 4 + r] = p2;
        }
    }
}

// ---------------------------------------------------------------------------
// Kernel 2: per (b,i) row — dedup 8 edges, softmax over unique neighbors,
// attn-weighted gather of h rows, elu. One warp per row; lane f covers
// features {f, f+32}. Gathered h rows are L2-resident (16.7 MB total).
// NOTE: edges are int32 on device (JAX x64 disabled -> int64 request degrades
// to int32).
// ---------------------------------------------------------------------------
__global__ __launch_bounds__(256) void gat_agg(const int* __restrict__ edges,
                                               float* __restrict__ out)
{
    const int g    = (blockIdx.x * 256 + threadIdx.x) >> 5;   // row in [0, 65536)
    const int lane = threadIdx.x & 31;
    const int b    = g >> 10;

    const float* hb  = g_h + (size_t)b * (Nn * Fdim);
    const float* s2b = g_s2 + b * Nn;

    int   ej  = 0;
    float s2v = 0.f;
    if (lane < DEG) {
        ej  = edges[(size_t)g * DEG + lane] & (Nn - 1);  // clamp: wild addr impossible
        s2v = s2b[ej];
    }
    const float s1g = g_s1[g];

    int   e8[DEG];
    float s28[DEG];
    #pragma unroll
    for (int m = 0; m < DEG; m++) {
        e8[m]  = __shfl_sync(0xffffffffu, ej, m);
        s28[m] = __shfl_sync(0xffffffffu, s2v, m);
    }

    // LeakyReLU logits with duplicate suppression (adj is a boolean set).
    float w[DEG];
    float mx = -1e30f;
    #pragma unroll
    for (int m = 0; m < DEG; m++) {
        float ev = s1g + s28[m];
        ev = ev > 0.f ? ev : ALPHA * ev;
        bool dup = false;
        #pragma unroll
        for (int n = 0; n < m; n++) dup = dup || (e8[n] == e8[m]);
        w[m] = dup ? -1e30f : ev;
        mx = fmaxf(mx, w[m]);
    }
    float den = 0.f;
    #pragma unroll
    for (int m = 0; m < DEG; m++) {
        w[m] = (w[m] == -1e30f) ? 0.f : expf(w[m] - mx);
        den += w[m];
    }
    const float inv = 1.f / den;

    float acc0 = 0.f, acc1 = 0.f;
    #pragma unroll
    for (int m = 0; m < DEG; m++) {
        const float* hr = hb + e8[m] * 64;
        const float wm = w[m] * inv;
        acc0 = fmaf(wm, hr[lane],      acc0);
        acc1 = fmaf(wm, hr[lane + 32], acc1);
    }

    out[(size_t)g * 64 + lane]      = acc0 > 0.f ? acc0 : expm1f(acc0);
    out[(size_t)g * 64 + lane + 32] = acc1 > 0.f ? acc1 : expm1f(acc1);
}

// ---------------------------------------------------------------------------
extern "C" void kernel_launch(void* const* d_in, const int* in_sizes, int n_in,
                              void* d_out, int out_size) {
    // Bind inputs BY ELEMENT COUNT (all four sizes are distinct) so that the
    // metadata ordering can never produce a mis-cast pointer.
    const float* atoms = nullptr;   // 64*1024*64 = 4194304 (f32)
    const int*   edges = nullptr;   // 64*1024*8  = 524288  (i32: jax x64 off)
    const float* W     = nullptr;   // 64*64      = 4096    (f32)
    const float* a     = nullptr;   // 2*64*1     = 128     (f32)

    for (int i = 0; i < n_in; i++) {
        switch (in_sizes[i]) {
            case 4194304: atoms = (const float*)d_in[i]; break;
            case 524288:  edges = (const int*)d_in[i];   break;
            case 4096:    W     = (const float*)d_in[i]; break;
            case 128:     a     = (const float*)d_in[i]; break;
            default: break;
        }
    }
    if (!atoms || !edges || !W || !a) return;  // defensive; should not happen

    float* out = (float*)d_out;

    gat_gemm<<<(Bb * Nn) / 64, 256>>>(atoms, W, a);
    gat_agg<<<(Bb * Nn) / 8, 256>>>(edges, out);
}

// round 4
// speedup vs baseline: 1.2093x; 1.2093x over previous
#include <cuda_runtime.h>
#include <math.h>

#define Bb 64
#define Nn 1024
#define Fdim 64
#define DEG 8
#define ALPHA 0.2f

// Scratch (static __device__ globals — allocation-free per harness rules)
__device__ __align__(16) float g_h[Bb * Nn * Fdim];    // 16 MB: h = atoms @ W
__device__ float g_s1[Bb * Nn];                        // h @ a1
__device__ float g_s2[Bb * Nn];                        // h @ a2
__device__ __align__(16) float g_w[Bb * Nn * DEG];     // 2 MB: normalized softmax weights

// Packed f32x2 FMA (sm_100+): d.lo += a.lo*b.lo; d.hi += a.hi*b.hi
__device__ __forceinline__ void fma2(unsigned long long& d,
                                     unsigned long long a,
                                     unsigned long long b) {
    asm("fma.rn.f32x2 %0, %1, %2, %0;" : "+l"(d) : "l"(a), "l"(b));
}
__device__ __forceinline__ float2 up64(unsigned long long v) {
    float2 r;
    r.x = __uint_as_float((unsigned)v);
    r.y = __uint_as_float((unsigned)(v >> 32));
    return r;
}

// ---------------------------------------------------------------------------
// Kernel 1: h = atoms @ W (65536 x 64 x 64) with packed f32x2 FMA.
// Block = 256 threads, 64 rows. Thread (tr, tc) owns a 4x4 tile, accumulated
// as 8 f32x2 (rows x col-pairs). A-tile stored DUPLICATED (v,v) in smem so the
// broadcast operand of fma.f32x2 loads directly; W col-pairs come free from
// layout. Inner loop: 3 LDS.128 + 8 FFMA2 per k (vs 2 LDS + 16 FFMA before).
// s1 = h@a1, s2 = h@a2 fused in epilogue.
// ---------------------------------------------------------------------------
__global__ __launch_bounds__(256, 4) void gat_gemm(const float* __restrict__ atoms,
                                                   const float* __restrict__ W,
                                                   const float* __restrict__ a)
{
    extern __shared__ __align__(16) char dsm[];
    float2* sATd = (float2*)dsm;                         // [64 k][66 row-pad] duplicated
    float*  sW   = (float*)(dsm + 64 * 66 * sizeof(float2));  // [64 k][64 c]

    const int tid  = threadIdx.x;
    const int row0 = blockIdx.x * 64;

    #pragma unroll
    for (int i = tid; i < 4096; i += 256) sW[i] = W[i];

    #pragma unroll
    for (int i = tid; i < 4096; i += 256) {
        int r = i >> 6, k = i & 63;
        float v = atoms[(size_t)(row0 + r) * 64 + k];
        sATd[k * 66 + r] = make_float2(v, v);
    }
    __syncthreads();

    const int tc = tid & 15;   // col group: cols 4*tc .. 4*tc+3
    const int tr = tid >> 4;   // row group: rows 4*tr .. 4*tr+3

    unsigned long long acc[4][2];
    #pragma unroll
    for (int r = 0; r < 4; r++) { acc[r][0] = 0ULL; acc[r][1] = 0ULL; }

    #pragma unroll 8
    for (int k = 0; k < 64; k++) {
        // rows (4tr..4tr+3) duplicated: two LDS.128 give 4 x (a,a) packs
        ulonglong2 a01 = *(const ulonglong2*)&sATd[k * 66 + tr * 4];
        ulonglong2 a23 = *(const ulonglong2*)&sATd[k * 66 + tr * 4 + 2];
        // cols (4tc..4tc+3): one LDS.128 gives (w0,w1),(w2,w3) packs
        ulonglong2 wq  = *(const ulonglong2*)&sW[k * 64 + tc * 4];
        fma2(acc[0][0], a01.x, wq.x); fma2(acc[0][1], a01.x, wq.y);
        fma2(acc[1][0], a01.y, wq.x); fma2(acc[1][1], a01.y, wq.y);
        fma2(acc[2][0], a23.x, wq.x); fma2(acc[2][1], a23.x, wq.y);
        fma2(acc[3][0], a23.y, wq.x); fma2(acc[3][1], a23.y, wq.y);
    }

    float a1v[4], a2v[4];
    #pragma unroll
    for (int c = 0; c < 4; c++) {
        a1v[c] = a[tc * 4 + c];
        a2v[c] = a[64 + tc * 4 + c];
    }

    #pragma unroll
    for (int r = 0; r < 4; r++) {
        float2 u0 = up64(acc[r][0]);
        float2 u1 = up64(acc[r][1]);
        float4 hv = make_float4(u0.x, u0.y, u1.x, u1.y);
        *reinterpret_cast<float4*>(&g_h[(size_t)(row0 + tr * 4 + r) * 64 + tc * 4]) = hv;

        float p1 = u0.x * a1v[0];
        p1 = fmaf(u0.y, a1v[1], p1);
        p1 = fmaf(u1.x, a1v[2], p1);
        p1 = fmaf(u1.y, a1v[3], p1);
        float p2 = u0.x * a2v[0];
        p2 = fmaf(u0.y, a2v[1], p2);
        p2 = fmaf(u1.x, a2v[2], p2);
        p2 = fmaf(u1.y, a2v[3], p2);
        #pragma unroll
        for (int off = 8; off > 0; off >>= 1) {
            p1 += __shfl_xor_sync(0xffffffffu, p1, off);
            p2 += __shfl_xor_sync(0xffffffffu, p2, off);
        }
        if (tc == 0) {
            g_s1[row0 + tr * 4 + r] = p1;
            g_s2[row0 + tr * 4 + r] = p2;
        }
    }
}

// ---------------------------------------------------------------------------
// Kernel 2: per-row softmax weight precompute. ONE THREAD per row: dedup,
// leaky-relu logits, softmax over <=8 unique neighbors, write normalized
// weights. The -9e15 mask underflows to exact 0 after exp in fp32, so this is
// bit-equivalent to the dense reference softmax.
// ---------------------------------------------------------------------------
__global__ __launch_bounds__(256) void gat_weights(const int* __restrict__ edges)
{
    const int g = blockIdx.x * 256 + threadIdx.x;      // row in [0, 65536)
    const int b = g >> 10;
    const float* s2b = g_s2 + (b << 10);

    const int4 ea = __ldg(&((const int4*)edges)[2 * g]);
    const int4 eb = __ldg(&((const int4*)edges)[2 * g + 1]);
    int e[DEG] = { ea.x & (Nn - 1), ea.y & (Nn - 1), ea.z & (Nn - 1), ea.w & (Nn - 1),
                   eb.x & (Nn - 1), eb.y & (Nn - 1), eb.z & (Nn - 1), eb.w & (Nn - 1) };

    const float s1g = g_s1[g];

    float w[DEG];
    float mx = -1e30f;
    #pragma unroll
    for (int m = 0; m < DEG; m++) {
        float ev = s1g + __ldg(&s2b[e[m]]);
        ev = ev > 0.f ? ev : ALPHA * ev;
        bool dup = false;
        #pragma unroll
        for (int n = 0; n < m; n++) dup = dup || (e[n] == e[m]);
        w[m] = dup ? -1e30f : ev;
        mx = fmaxf(mx, w[m]);
    }
    float den = 0.f;
    #pragma unroll
    for (int m = 0; m < DEG; m++) {
        w[m] = (w[m] == -1e30f) ? 0.f : __expf(w[m] - mx);
        den += w[m];
    }
    const float inv = 1.f / den;

    ((float4*)g_w)[2 * g]     = make_float4(w[0] * inv, w[1] * inv, w[2] * inv, w[3] * inv);
    ((float4*)g_w)[2 * g + 1] = make_float4(w[4] * inv, w[5] * inv, w[6] * inv, w[7] * inv);
}

// ---------------------------------------------------------------------------
// Kernel 3: aggregation. Warp per row; edges+weights read as UNIFORM vector
// loads (warp broadcast, zero shfl). Each lane owns cols {2*lane, 2*lane+1}
// as a float2: 8 gather LDG.64 + 16 FMA + ELU + 1 STG.64 per lane.
// h gathers are L2-resident (16.7 MB total).
// ---------------------------------------------------------------------------
__global__ __launch_bounds__(256) void gat_agg(const int* __restrict__ edges,
                                               float* __restrict__ out)
{
    const int g    = (blockIdx.x * 256 + threadIdx.x) >> 5;   // row in [0, 65536)
    const int lane = threadIdx.x & 31;
    const int b    = g >> 10;

    const float2* hb = (const float2*)(g_h + ((size_t)b << 16));

    const int4   ea = __ldg(&((const int4*)edges)[2 * g]);
    const int4   eb = __ldg(&((const int4*)edges)[2 * g + 1]);
    const float4 wa = __ldg(&((const float4*)g_w)[2 * g]);
    const float4 wb = __ldg(&((const float4*)g_w)[2 * g + 1]);

    float2 acc = make_float2(0.f, 0.f);
    #define GAT_STEP(E, Wv) { \
        const float2 hv = __ldg(&hb[((E) & (Nn - 1)) * 32 + lane]); \
        acc.x = fmaf((Wv), hv.x, acc.x); \
        acc.y = fmaf((Wv), hv.y, acc.y); }
    GAT_STEP(ea.x, wa.x) GAT_STEP(ea.y, wa.y) GAT_STEP(ea.z, wa.z) GAT_STEP(ea.w, wa.w)
    GAT_STEP(eb.x, wb.x) GAT_STEP(eb.y, wb.y) GAT_STEP(eb.z, wb.z) GAT_STEP(eb.w, wb.w)
    #undef GAT_STEP

    float2 o;
    o.x = acc.x > 0.f ? acc.x : expm1f(acc.x);
    o.y = acc.y > 0.f ? acc.y : expm1f(acc.y);
    ((float2*)out)[(size_t)g * 32 + lane] = o;
}

// ---------------------------------------------------------------------------
extern "C" void kernel_launch(void* const* d_in, const int* in_sizes, int n_in,
                              void* d_out, int out_size) {
    // Bind inputs BY ELEMENT COUNT (all four sizes distinct) — order-proof.
    const float* atoms = nullptr;   // 64*1024*64 = 4194304 (f32)
    const int*   edges = nullptr;   // 64*1024*8  = 524288  (i32: jax x64 off)
    const float* W     = nullptr;   // 64*64      = 4096    (f32)
    const float* a     = nullptr;   // 2*64*1     = 128     (f32)

    for (int i = 0; i < n_in; i++) {
        switch (in_sizes[i]) {
            case 4194304: atoms = (const float*)d_in[i]; break;
            case 524288:  edges = (const int*)d_in[i];   break;
            case 4096:    W     = (const float*)d_in[i]; break;
            case 128:     a     = (const float*)d_in[i]; break;
            default: break;
        }
    }
    if (!atoms || !edges || !W || !a) return;

    float* out = (float*)d_out;

    const int smem = 64 * 66 * sizeof(float2) + 64 * 64 * sizeof(float);  // 50176
    cudaFuncSetAttribute(gat_gemm, cudaFuncAttributeMaxDynamicSharedMemorySize, smem);

    gat_gemm<<<(Bb * Nn) / 64, 256, smem>>>(atoms, W, a);
    gat_weights<<<(Bb * Nn) / 256, 256>>>(edges);
    gat_agg<<<(Bb * Nn) / 8, 256>>>(edges, out);
}

// round 6
// speedup vs baseline: 1.3846x; 1.1450x over previous
#include <cuda_runtime.h>
#include <cuda_fp16.h>
#include <math.h>

#define Bb 64
#define Nn 1024
#define Fdim 64
#define DEG 8
#define ALPHA 0.2f

// Scratch (static __device__ globals — allocation-free per harness rules)
__device__ float g_s1[Bb * Nn];                         // h @ a1 (fp32)
__device__ float g_s2[Bb * Nn];                         // h @ a2 (fp32)
__device__ __align__(16) float   g_w[Bb * Nn * DEG];    // 2 MB: normalized softmax weights
__device__ __align__(16) __half2 g_h2[Bb * Nn * 32];    // 8 MB: h in fp16 (gather operand)

#define SAT_PITCH 260   // floats; 260*4=1040 B, 16B-aligned rows, 4-way-max store conflicts

__device__ __forceinline__ unsigned h2u(__half2 v) {
    return *reinterpret_cast<unsigned*>(&v);            // register bit-cast, no SASS cost
}

// ---------------------------------------------------------------------------
// Kernel 1: h = atoms @ W (65536 x 64 x 64), scalar FFMA, 8x8 per thread.
// Block = 256 threads covers 256 rows x 64 cols. Thread (rg, cg):
// rows 8*rg..+7, cols 8*cg..+7. Inner loop: 4 LDS.128 + 64 FFMA per k
// (16 FMA per LDS -> FFMA-pipe bound, not LSU bound).
// Epilogue: s1 = h@a1, s2 = h@a2 (fp32, butterfly over the 8 col-groups),
// and h stored as half2 for the gather kernel. No fp32 h is kept.
// ---------------------------------------------------------------------------
__global__ __launch_bounds__(256) void gat_gemm(const float* __restrict__ atoms,
                                                const float* __restrict__ W,
                                                const float* __restrict__ a)
{
    extern __shared__ __align__(16) float sm[];
    float* sAT = sm;                       // [64 k][SAT_PITCH] (row-transposed atoms)
    float* sW  = sm + 64 * SAT_PITCH;      // [64 k][64 c]

    const int tid  = threadIdx.x;
    const int row0 = blockIdx.x * 256;

    #pragma unroll
    for (int i = tid; i < 4096; i += 256) sW[i] = W[i];

    // 256 rows x 64 k, transposed: coalesced gmem reads, strided smem stores
    #pragma unroll
    for (int i = tid; i < 16384; i += 256) {
        int r = i >> 6, k = i & 63;
        sAT[k * SAT_PITCH + r] = atoms[(size_t)(row0 + r) * 64 + k];
    }
    __syncthreads();

    const int cg = tid & 7;    // col group: cols 8*cg..+7
    const int rg = tid >> 3;   // row group: rows 8*rg..+7

    float acc[8][8];
    #pragma unroll
    for (int r = 0; r < 8; r++)
        #pragma unroll
        for (int c = 0; c < 8; c++) acc[r][c] = 0.f;

    #pragma unroll 4
    for (int k = 0; k < 64; k++) {
        const float* Ak = &sAT[k * SAT_PITCH + rg * 8];
        const float* Wk = &sW[k * 64 + cg * 8];
        float4 a0 = *(const float4*)(Ak);
        float4 a1 = *(const float4*)(Ak + 4);
        float4 w0 = *(const float4*)(Wk);
        float4 w1 = *(const float4*)(Wk + 4);
        float ar[8] = {a0.x, a0.y, a0.z, a0.w, a1.x, a1.y, a1.z, a1.w};
        float wr[8] = {w0.x, w0.y, w0.z, w0.w, w1.x, w1.y, w1.z, w1.w};
        #pragma unroll
        for (int r = 0; r < 8; r++)
            #pragma unroll
            for (int c = 0; c < 8; c++)
                acc[r][c] = fmaf(ar[r], wr[c], acc[r][c]);
    }

    // a1/a2 slices for this thread's 8 cols
    float a1v[8], a2v[8];
    #pragma unroll
    for (int c = 0; c < 8; c++) {
        a1v[c] = a[cg * 8 + c];
        a2v[c] = a[64 + cg * 8 + c];
    }

    #pragma unroll
    for (int r = 0; r < 8; r++) {
        const int row = row0 + rg * 8 + r;

        // fp16 h store: 8 cols = 4 half2 = one 16B store, coalesced across cg
        uint4 pk;
        pk.x = h2u(__floats2half2_rn(acc[r][0], acc[r][1]));
        pk.y = h2u(__floats2half2_rn(acc[r][2], acc[r][3]));
        pk.z = h2u(__floats2half2_rn(acc[r][4], acc[r][5]));
        pk.w = h2u(__floats2half2_rn(acc[r][6], acc[r][7]));
        *reinterpret_cast<uint4*>(&g_h2[(size_t)row * 32 + cg * 4]) = pk;

        // s1/s2 partials over this thread's 8 cols (fp32 accs), reduce over cg
        float p1 = 0.f, p2 = 0.f;
        #pragma unroll
        for (int c = 0; c < 8; c++) {
            p1 = fmaf(acc[r][c], a1v[c], p1);
            p2 = fmaf(acc[r][c], a2v[c], p2);
        }
        #pragma unroll
        for (int off = 4; off > 0; off >>= 1) {
            p1 += __shfl_xor_sync(0xffffffffu, p1, off);
            p2 += __shfl_xor_sync(0xffffffffu, p2, off);
        }
        if (cg == 0) {
            g_s1[row] = p1;
            g_s2[row] = p2;
        }
    }
}

// ---------------------------------------------------------------------------
// Kernel 2: per-row softmax weight precompute. ONE THREAD per row: dedup,
// leaky-relu logits, softmax over <=8 unique neighbors, write normalized
// weights. The -9e15 mask underflows to exact 0 after exp in fp32, so this is
// equivalent to the dense reference softmax.
// ---------------------------------------------------------------------------
__global__ __launch_bounds__(256) void gat_weights(const int* __restrict__ edges)
{
    const int g = blockIdx.x * 256 + threadIdx.x;      // row in [0, 65536)
    const int b = g >> 10;
    const float* s2b = g_s2 + (b << 10);

    const int4 ea = __ldg(&((const int4*)edges)[2 * g]);
    const int4 eb = __ldg(&((const int4*)edges)[2 * g + 1]);
    int e[DEG] = { ea.x & (Nn - 1), ea.y & (Nn - 1), ea.z & (Nn - 1), ea.w & (Nn - 1),
                   eb.x & (Nn - 1), eb.y & (Nn - 1), eb.z & (Nn - 1), eb.w & (Nn - 1) };

    const float s1g = g_s1[g];

    float w[DEG];
    float mx = -1e30f;
    #pragma unroll
    for (int m = 0; m < DEG; m++) {
        float ev = s1g + __ldg(&s2b[e[m]]);
        ev = ev > 0.f ? ev : ALPHA * ev;
        bool dup = false;
        #pragma unroll
        for (int n = 0; n < m; n++) dup = dup || (e[n] == e[m]);
        w[m] = dup ? -1e30f : ev;
        mx = fmaxf(mx, w[m]);
    }
    float den = 0.f;
    #pragma unroll
    for (int m = 0; m < DEG; m++) {
        w[m] = (w[m] == -1e30f) ? 0.f : __expf(w[m] - mx);
        den += w[m];
    }
    const float inv = 1.f / den;

    ((float4*)g_w)[2 * g]     = make_float4(w[0] * inv, w[1] * inv, w[2] * inv, w[3] * inv);
    ((float4*)g_w)[2 * g + 1] = make_float4(w[4] * inv, w[5] * inv, w[6] * inv, w[7] * inv);
}

// ---------------------------------------------------------------------------
// Kernel 3: aggregation. Warp per row; edges+weights via uniform vector loads
// (warp-broadcast, zero shfl). Lane owns cols {2*lane, 2*lane+1}: 8 gather
// LDG.32 of half2 (128 B per gathered row -> full sectors) + fp32 FMA + ELU.
// fp16 h halves the L2 gather traffic vs fp32.
// ---------------------------------------------------------------------------
__global__ __launch_bounds__(256) void gat_agg(const int* __restrict__ edges,
                                               float* __restrict__ out)
{
    const int g    = (blockIdx.x * 256 + threadIdx.x) >> 5;   // row in [0, 65536)
    const int lane = threadIdx.x & 31;
    const int b    = g >> 10;

    const __half2* hb = g_h2 + ((size_t)b << 15);   // batch base: 1024 rows * 32 half2

    const int4   ea = __ldg(&((const int4*)edges)[2 * g]);
    const int4   eb = __ldg(&((const int4*)edges)[2 * g + 1]);
    const float4 wa = __ldg(&((const float4*)g_w)[2 * g]);
    const float4 wb = __ldg(&((const float4*)g_w)[2 * g + 1]);

    float2 acc = make_float2(0.f, 0.f);
    #define GAT_STEP(E, Wv) { \
        const float2 hv = __half22float2(__ldg(&hb[((E) & (Nn - 1)) * 32 + lane])); \
        acc.x = fmaf((Wv), hv.x, acc.x); \
        acc.y = fmaf((Wv), hv.y, acc.y); }
    GAT_STEP(ea.x, wa.x) GAT_STEP(ea.y, wa.y) GAT_STEP(ea.z, wa.z) GAT_STEP(ea.w, wa.w)
    GAT_STEP(eb.x, wb.x) GAT_STEP(eb.y, wb.y) GAT_STEP(eb.z, wb.z) GAT_STEP(eb.w, wb.w)
    #undef GAT_STEP

    float2 o;
    o.x = acc.x > 0.f ? acc.x : expm1f(acc.x);
    o.y = acc.y > 0.f ? acc.y : expm1f(acc.y);
    ((float2*)out)[(size_t)g * 32 + lane] = o;
}

// ---------------------------------------------------------------------------
extern "C" void kernel_launch(void* const* d_in, const int* in_sizes, int n_in,
                              void* d_out, int out_size) {
    // Bind inputs BY ELEMENT COUNT (all four sizes distinct) — order-proof.
    const float* atoms = nullptr;   // 64*1024*64 = 4194304 (f32)
    const int*   edges = nullptr;   // 64*1024*8  = 524288  (i32: jax x64 off)
    const float* W     = nullptr;   // 64*64      = 4096    (f32)
    const float* a     = nullptr;   // 2*64*1     = 128     (f32)

    for (int i = 0; i < n_in; i++) {
        switch (in_sizes[i]) {
            case 4194304: atoms = (const float*)d_in[i]; break;
            case 524288:  edges = (const int*)d_in[i];   break;
            case 4096:    W     = (const float*)d_in[i]; break;
            case 128:     a     = (const float*)d_in[i]; break;
            default: break;
        }
    }
    if (!atoms || !edges || !W || !a) return;

    float* out = (float*)d_out;

    const int smem = (64 * SAT_PITCH + 64 * 64) * sizeof(float);  // 82944 B
    cudaFuncSetAttribute(gat_gemm, cudaFuncAttributeMaxDynamicSharedMemorySize, smem);

    gat_gemm<<<(Bb * Nn) / 256, 256, smem>>>(atoms, W, a);
    gat_weights<<<(Bb * Nn) / 256, 256>>>(edges);
    gat_agg<<<(Bb * Nn) / 8, 256>>>(edges, out);
}